// round 6
// baseline (speedup 1.0000x reference)
#include <cuda_runtime.h>
#include <math.h>

// Problem constants
#define TT 512     // timesteps
#define BB 64      // batch
#define II 512     // input dim
#define HH 1024    // hidden dim
#define G4 4096    // 4*H gate dim
#define NSTEP 1024 // TT * NUM_LAYERS
#define NBLK 128   // persistent blocks (<= SM count, all co-resident)

// Scratch: precomputed input projection Xg[t][b][4H] = x@Ww.T + bw + bu  (512 MB)
__device__ float g_xg[(size_t)TT * BB * G4];

// Grid barrier state (sense-reversing; returns to {0,0} after every launch
// because 1024 barriers = even number of sense flips)
__device__ int g_count;
__device__ int g_sense;

// Packed dual fp32 FMA: d.lo += a.lo*b.lo ; d.hi += a.hi*b.hi  (one instr)
__device__ __forceinline__ void ffma2(unsigned long long& d,
                                      unsigned long long a,
                                      unsigned long long b)
{
    asm("fma.rn.f32x2 %0, %1, %2, %0;" : "+l"(d) : "l"(a), "l"(b));
}
__device__ __forceinline__ float f2_lo(unsigned long long v) {
    return __uint_as_float((unsigned)(v & 0xffffffffu));
}
__device__ __forceinline__ float f2_hi(unsigned long long v) {
    return __uint_as_float((unsigned)(v >> 32));
}

// ---------------------------------------------------------------------------
// Kernel 1: Xg = x @ Ww.T + (bw + bu)
// M = TT*BB = 32768 rows (row r -> t = r/64, b = r%64), N = 4096, K = 512.
// 128x128 tile, BK=16, 256 threads, 8x8 microtile via FFMA2:
//   accumulators packed along rows (row pairs), B duplicated in SMEM.
// ---------------------------------------------------------------------------
#define XG_BM 128
#define XG_BN 128
#define XG_BK 16

__global__ __launch_bounds__(256) void xg_kernel(
    const float* __restrict__ x,   // [B, T, I]
    const float* __restrict__ Ww,  // [4H, I]
    const float* __restrict__ bw,  // [4H]
    const float* __restrict__ bu)  // [4H]
{
    __shared__ __align__(16) float As[XG_BK][XG_BM + 4];        // stride 132 (16B mult)
    __shared__ __align__(16) float Bs2[XG_BK][2 * XG_BN + 8];   // dup cols, stride 264

    const int tid = threadIdx.x;
    const int m0 = blockIdx.y * XG_BM;
    const int n0 = blockIdx.x * XG_BN;
    const int ty = tid >> 4;   // 0..15 -> rows ty*8 .. ty*8+7
    const int tx = tid & 15;   // 0..15 -> cols tx*8 .. tx*8+7

    // acc[p][j]: row pair p (rows ty*8+2p, +1), col tx*8+j
    unsigned long long acc[4][8];
#pragma unroll
    for (int p = 0; p < 4; p++)
#pragma unroll
        for (int j = 0; j < 8; j++) acc[p][j] = 0ull;

    for (int k0 = 0; k0 < II; k0 += XG_BK) {
        // Load A tile: 128 rows x 16 k = 512 float4, 2 per thread
#pragma unroll
        for (int l = 0; l < 2; l++) {
            int fq = l * 256 + tid;       // 0..511
            int r  = fq >> 2;             // 0..127
            int kq = (fq & 3) * 4;        // 0,4,8,12
            int gr = m0 + r;
            int b  = gr & 63;
            int t  = gr >> 6;
            const float4 v = *(const float4*)(x + ((size_t)(b * TT + t)) * II + k0 + kq);
            As[kq + 0][r] = v.x;
            As[kq + 1][r] = v.y;
            As[kq + 2][r] = v.z;
            As[kq + 3][r] = v.w;
        }
        // Load B tile duplicated: Ww rows n0..n0+127, 16 k
#pragma unroll
        for (int l = 0; l < 2; l++) {
            int fq = l * 256 + tid;
            int n  = fq >> 2;
            int kq = (fq & 3) * 4;
            const float4 v = *(const float4*)(Ww + (size_t)(n0 + n) * II + k0 + kq);
            *(float2*)&Bs2[kq + 0][2 * n] = make_float2(v.x, v.x);
            *(float2*)&Bs2[kq + 1][2 * n] = make_float2(v.y, v.y);
            *(float2*)&Bs2[kq + 2][2 * n] = make_float2(v.z, v.z);
            *(float2*)&Bs2[kq + 3][2 * n] = make_float2(v.w, v.w);
        }
        __syncthreads();

#pragma unroll
        for (int kk = 0; kk < XG_BK; kk++) {
            // 4 row pairs
            const ulonglong2 a01 = *(const ulonglong2*)&As[kk][ty * 8];
            const ulonglong2 a23 = *(const ulonglong2*)&As[kk][ty * 8 + 4];
            // 8 dup col pairs
            const ulonglong2 b01 = *(const ulonglong2*)&Bs2[kk][16 * tx];
            const ulonglong2 b23 = *(const ulonglong2*)&Bs2[kk][16 * tx + 4];
            const ulonglong2 b45 = *(const ulonglong2*)&Bs2[kk][16 * tx + 8];
            const ulonglong2 b67 = *(const ulonglong2*)&Bs2[kk][16 * tx + 12];
            unsigned long long ar[4] = {a01.x, a01.y, a23.x, a23.y};
            unsigned long long br[8] = {b01.x, b01.y, b23.x, b23.y,
                                        b45.x, b45.y, b67.x, b67.y};
#pragma unroll
            for (int p = 0; p < 4; p++)
#pragma unroll
                for (int j = 0; j < 8; j++)
                    ffma2(acc[p][j], ar[p], br[j]);
        }
        __syncthreads();
    }

    // Epilogue: add biases, store (vectorized per row)
    float bsum[8];
#pragma unroll
    for (int j = 0; j < 8; j++) {
        int gn = n0 + tx * 8 + j;
        bsum[j] = bw[gn] + bu[gn];
    }
#pragma unroll
    for (int p = 0; p < 4; p++) {
#pragma unroll
        for (int half = 0; half < 2; half++) {
            int gm = m0 + ty * 8 + 2 * p + half;
            float* row = g_xg + (size_t)gm * G4 + n0 + tx * 8;
            float4 v0, v1;
            float r0 = half ? f2_hi(acc[p][0]) : f2_lo(acc[p][0]);
            float r1 = half ? f2_hi(acc[p][1]) : f2_lo(acc[p][1]);
            float r2 = half ? f2_hi(acc[p][2]) : f2_lo(acc[p][2]);
            float r3 = half ? f2_hi(acc[p][3]) : f2_lo(acc[p][3]);
            float r4 = half ? f2_hi(acc[p][4]) : f2_lo(acc[p][4]);
            float r5 = half ? f2_hi(acc[p][5]) : f2_lo(acc[p][5]);
            float r6 = half ? f2_hi(acc[p][6]) : f2_lo(acc[p][6]);
            float r7 = half ? f2_hi(acc[p][7]) : f2_lo(acc[p][7]);
            v0.x = r0 + bsum[0]; v0.y = r1 + bsum[1];
            v0.z = r2 + bsum[2]; v0.w = r3 + bsum[3];
            v1.x = r4 + bsum[4]; v1.y = r5 + bsum[5];
            v1.z = r6 + bsum[6]; v1.w = r7 + bsum[7];
            *(float4*)(row)     = v0;
            *(float4*)(row + 4) = v1;
        }
    }
}

// ---------------------------------------------------------------------------
// Sense-reversing grid barrier. All NBLK blocks are resident (grid <= SMs).
// ---------------------------------------------------------------------------
__device__ __forceinline__ void grid_barrier(int* lsense)
{
    __syncthreads();
    if (threadIdx.x == 0) {
        int ns = *lsense ^ 1;
        __threadfence();
        if (atomicAdd(&g_count, 1) == NBLK - 1) {
            g_count = 0;
            __threadfence();
            *(volatile int*)&g_sense = ns;
        } else {
            while (*(volatile int*)&g_sense != ns) { }
        }
        __threadfence();
        *lsense = ns;
    }
    __syncthreads();
}

// ---------------------------------------------------------------------------
// Kernel 2: persistent recurrence. 128 blocks x 256 threads, loops s=0..1023.
// Block owns 8 h-columns j0..j0+7 -> 32 gate columns:
//   gate col c (0..31) -> global gate index (c/8)*1024 + j0 + (c%8)
// Split-K: group g = tid/128 accumulates K half [g*512, g*512+512).
// Within group: 64x32 tile, 128 threads, 4x4 micro via FFMA2
// (row pairs free from Hs, Us duplicated in SMEM for LDS.64 dup pairs).
// c state lives in registers (each thread owns its 2 cells across all steps);
// Xg[t] is prefetched into registers at step start so DRAM latency hides
// under the GEMM. hprev streams via __ldcg so the Uw slice stays L1-resident.
// ---------------------------------------------------------------------------
#define KC 32
#define NCHUNK 16   // 512 / KC per group

__global__ __launch_bounds__(256) void lstm_persistent(
    const float* __restrict__ Uw,  // [4H, H]
    float* __restrict__ out)       // [2, NSTEP, B, H]
{
    __shared__ __align__(16) float Hs[2][KC][68];    // stride 272B (16B mult)
    __shared__ __align__(16) float Us2[2][KC][72];   // dup cols (64 used), 288B
    __shared__ float Gs[2][BB][33];                  // per-group gate partials

    const int tid = threadIdx.x;        // 256
    const int j0  = blockIdx.x * 8;     // 128 blocks
    const int g   = tid >> 7;           // k-half group 0/1
    const int gt  = tid & 127;
    const int tr  = gt & 15;            // rows 4*tr .. 4*tr+3
    const int tc  = gt >> 4;            // cols 4*tc .. 4*tc+3
    int lsense = 0;

    const size_t step_sz = (size_t)BB * HH;          // 65536
    const size_t c_base  = (size_t)NSTEP * step_sz;

    // Hs fill coordinates: 4 float4 per thread
    int hb[4], hk[4];
#pragma unroll
    for (int l = 0; l < 4; l++) {
        int fq = l * 128 + gt;          // 0..511
        hb[l] = fq >> 3;                // b 0..63
        hk[l] = (fq & 7) * 4;           // kq 0..28
    }
    // Us fill coordinates: 2 float4 per thread
    int uc[2], uk[2];
    size_t urow[2];
#pragma unroll
    for (int l = 0; l < 2; l++) {
        int fq = l * 128 + gt;          // 0..255
        uc[l] = fq >> 3;                // c 0..31
        uk[l] = (fq & 7) * 4;
        int gc = (uc[l] >> 3) * HH + j0 + (uc[l] & 7);
        urow[l] = (size_t)gc * HH;
    }
    const int kbase0 = g * 512;

    // Epilogue cell coordinates (fixed across steps) + register-resident c
    int eb[2], ej[2];
    float creg[2];
#pragma unroll
    for (int l = 0; l < 2; l++) {
        int idx = l * 256 + tid;        // 0..511
        eb[l] = idx >> 3;               // b
        ej[l] = idx & 7;                // jj
        creg[l] = 0.f;
    }

    for (int s = 0; s < NSTEP; s++) {
        const int t = s >> 1;

        // Prefetch this step's Xg gate inputs (DRAM) — hides under the GEMM
        float xv[8];
        {
            const float* xgt = g_xg + ((size_t)t * BB) * G4;
#pragma unroll
            for (int l = 0; l < 2; l++) {
                const float* xrow = xgt + (size_t)eb[l] * G4 + j0 + ej[l];
                xv[l * 4 + 0] = __ldcg(xrow);
                xv[l * 4 + 1] = __ldcg(xrow + HH);
                xv[l * 4 + 2] = __ldcg(xrow + 2 * HH);
                xv[l * 4 + 3] = __ldcg(xrow + 3 * HH);
            }
        }

        // acc[p][j]: row pair p (rows 4tr+2p, +1), col 4tc+j
        unsigned long long acc[2][4];
#pragma unroll
        for (int p = 0; p < 2; p++)
#pragma unroll
            for (int j = 0; j < 4; j++) acc[p][j] = 0ull;

        if (s > 0) {
            const float* hprev = out + (size_t)(s - 1) * step_sz;

            // Prefetch chunk 0 into registers
            float4 hreg[4], ureg[2];
#pragma unroll
            for (int l = 0; l < 4; l++)
                hreg[l] = __ldcg((const float4*)(hprev + (size_t)hb[l] * HH + kbase0 + hk[l]));
#pragma unroll
            for (int l = 0; l < 2; l++)
                ureg[l] = *(const float4*)(Uw + urow[l] + kbase0 + uk[l]);

            for (int chunk = 0; chunk < NCHUNK; chunk++) {
                // Commit prefetched tile to shared (Us duplicated)
#pragma unroll
                for (int l = 0; l < 4; l++) {
                    Hs[g][hk[l] + 0][hb[l]] = hreg[l].x;
                    Hs[g][hk[l] + 1][hb[l]] = hreg[l].y;
                    Hs[g][hk[l] + 2][hb[l]] = hreg[l].z;
                    Hs[g][hk[l] + 3][hb[l]] = hreg[l].w;
                }
#pragma unroll
                for (int l = 0; l < 2; l++) {
                    *(float2*)&Us2[g][uk[l] + 0][2 * uc[l]] = make_float2(ureg[l].x, ureg[l].x);
                    *(float2*)&Us2[g][uk[l] + 1][2 * uc[l]] = make_float2(ureg[l].y, ureg[l].y);
                    *(float2*)&Us2[g][uk[l] + 2][2 * uc[l]] = make_float2(ureg[l].z, ureg[l].z);
                    *(float2*)&Us2[g][uk[l] + 3][2 * uc[l]] = make_float2(ureg[l].w, ureg[l].w);
                }
                __syncthreads();

                // Prefetch next chunk while computing this one
                if (chunk + 1 < NCHUNK) {
                    int kb = kbase0 + (chunk + 1) * KC;
#pragma unroll
                    for (int l = 0; l < 4; l++)
                        hreg[l] = __ldcg((const float4*)(hprev + (size_t)hb[l] * HH + kb + hk[l]));
#pragma unroll
                    for (int l = 0; l < 2; l++)
                        ureg[l] = *(const float4*)(Uw + urow[l] + kb + uk[l]);
                }

#pragma unroll
                for (int kk = 0; kk < KC; kk++) {
                    const ulonglong2 ap = *(const ulonglong2*)&Hs[g][kk][4 * tr];
                    const ulonglong2 b01 = *(const ulonglong2*)&Us2[g][kk][8 * tc];
                    const ulonglong2 b23 = *(const ulonglong2*)&Us2[g][kk][8 * tc + 4];
                    ffma2(acc[0][0], ap.x, b01.x);
                    ffma2(acc[0][1], ap.x, b01.y);
                    ffma2(acc[0][2], ap.x, b23.x);
                    ffma2(acc[0][3], ap.x, b23.y);
                    ffma2(acc[1][0], ap.y, b01.x);
                    ffma2(acc[1][1], ap.y, b01.y);
                    ffma2(acc[1][2], ap.y, b23.x);
                    ffma2(acc[1][3], ap.y, b23.y);
                }
                __syncthreads();
            }
        }

        // Stash group partials
#pragma unroll
        for (int p = 0; p < 2; p++)
#pragma unroll
            for (int j = 0; j < 4; j++) {
                Gs[g][4 * tr + 2 * p + 0][4 * tc + j] = f2_lo(acc[p][j]);
                Gs[g][4 * tr + 2 * p + 1][4 * tc + j] = f2_hi(acc[p][j]);
            }
        __syncthreads();

        // Fused LSTM cell epilogue: 512 cells, 2 per thread, c in registers
#pragma unroll
        for (int l = 0; l < 2; l++) {
            int b  = eb[l];
            int jj = ej[l];
            int j  = j0 + jj;

            float gi = Gs[0][b][jj]      + Gs[1][b][jj]      + xv[l * 4 + 0];
            float gf = Gs[0][b][8 + jj]  + Gs[1][b][8 + jj]  + xv[l * 4 + 1];
            float gg = Gs[0][b][16 + jj] + Gs[1][b][16 + jj] + xv[l * 4 + 2];
            float go = Gs[0][b][24 + jj] + Gs[1][b][24 + jj] + xv[l * 4 + 3];

            float si = 1.f / (1.f + __expf(-gi));
            float sf = 1.f / (1.f + __expf(-gf));
            float so = 1.f / (1.f + __expf(-go));
            float tg = tanhf(gg);

            float cn = creg[l] * sf + si * tg;
            float hn = so * tanhf(cn);
            creg[l] = cn;

            out[(size_t)s * step_sz + (size_t)b * HH + j]          = hn;
            out[c_base + (size_t)s * step_sz + (size_t)b * HH + j] = cn;
        }

        // Publish h of step s to all blocks before step s+1 reads it.
        grid_barrier(&lsense);
    }
}

// ---------------------------------------------------------------------------
extern "C" void kernel_launch(void* const* d_in, const int* in_sizes, int n_in,
                              void* d_out, int out_size)
{
    const float* x  = (const float*)d_in[0];
    const float* Ww = (const float*)d_in[1];
    const float* bw = (const float*)d_in[2];
    const float* Uw = (const float*)d_in[3];
    const float* bu = (const float*)d_in[4];
    float* out = (float*)d_out;

    dim3 g1(G4 / XG_BN, (TT * BB) / XG_BM);  // (32, 256)
    xg_kernel<<<g1, 256>>>(x, Ww, bw, bu);

    lstm_persistent<<<NBLK, 256>>>(Uw, out);
}

// round 7
// speedup vs baseline: 1.5893x; 1.5893x over previous
#include <cuda_runtime.h>
#include <math.h>

// Problem constants
#define TT 512     // timesteps
#define BB 64      // batch
#define II 512     // input dim
#define HH 1024    // hidden dim
#define G4 4096    // 4*H gate dim
#define NSTEP 1024 // TT * NUM_LAYERS
#define NBLK 128   // persistent blocks (<= SM count, all co-resident)

// Scratch: precomputed input projection Xg[t][b][4H] = x@Ww.T + bw + bu  (512 MB)
__device__ float g_xg[(size_t)TT * BB * G4];

// Grid barrier state (sense-reversing; returns to {0,0} after every launch
// because 1024 barriers = even number of sense flips)
__device__ int g_count;
__device__ int g_sense;

// ---------------------------------------------------------------------------
// Kernel 1: Xg = x @ Ww.T + (bw + bu)   (R4-proven plain-FFMA version)
// M = TT*BB = 32768 rows (row r -> t = r/64, b = r%64), N = 4096, K = 512.
// 128x128 tile, BK=16, 256 threads, 8x8 microtile.
// ---------------------------------------------------------------------------
#define XG_BM 128
#define XG_BN 128
#define XG_BK 16

__global__ __launch_bounds__(256) void xg_kernel(
    const float* __restrict__ x,   // [B, T, I]
    const float* __restrict__ Ww,  // [4H, I]
    const float* __restrict__ bw,  // [4H]
    const float* __restrict__ bu)  // [4H]
{
    __shared__ float As[XG_BK][XG_BM + 4];
    __shared__ float Bs[XG_BK][XG_BN + 4];

    const int tid = threadIdx.x;
    const int m0 = blockIdx.y * XG_BM;
    const int n0 = blockIdx.x * XG_BN;
    const int ty = tid >> 4;   // 0..15
    const int tx = tid & 15;   // 0..15

    float acc[8][8];
#pragma unroll
    for (int i = 0; i < 8; i++)
#pragma unroll
        for (int j = 0; j < 8; j++) acc[i][j] = 0.f;

    for (int k0 = 0; k0 < II; k0 += XG_BK) {
#pragma unroll
        for (int l = 0; l < 2; l++) {
            int fq = l * 256 + tid;       // 0..511
            int r  = fq >> 2;             // 0..127
            int kq = (fq & 3) * 4;        // 0,4,8,12
            int gr = m0 + r;
            int b  = gr & 63;
            int t  = gr >> 6;
            const float4 v = *(const float4*)(x + ((size_t)(b * TT + t)) * II + k0 + kq);
            As[kq + 0][r] = v.x;
            As[kq + 1][r] = v.y;
            As[kq + 2][r] = v.z;
            As[kq + 3][r] = v.w;
        }
#pragma unroll
        for (int l = 0; l < 2; l++) {
            int fq = l * 256 + tid;
            int n  = fq >> 2;
            int kq = (fq & 3) * 4;
            const float4 v = *(const float4*)(Ww + (size_t)(n0 + n) * II + k0 + kq);
            Bs[kq + 0][n] = v.x;
            Bs[kq + 1][n] = v.y;
            Bs[kq + 2][n] = v.z;
            Bs[kq + 3][n] = v.w;
        }
        __syncthreads();

#pragma unroll
        for (int kk = 0; kk < XG_BK; kk++) {
            float a[8], bb[8];
#pragma unroll
            for (int i = 0; i < 8; i++) a[i] = As[kk][ty * 8 + i];
#pragma unroll
            for (int j = 0; j < 8; j++) bb[j] = Bs[kk][tx * 8 + j];
#pragma unroll
            for (int i = 0; i < 8; i++)
#pragma unroll
                for (int j = 0; j < 8; j++) acc[i][j] += a[i] * bb[j];
        }
        __syncthreads();
    }

    float bsum[8];
#pragma unroll
    for (int j = 0; j < 8; j++) {
        int gn = n0 + tx * 8 + j;
        bsum[j] = bw[gn] + bu[gn];
    }
#pragma unroll
    for (int i = 0; i < 8; i++) {
        int gm = m0 + ty * 8 + i;
        float* row = g_xg + (size_t)gm * G4 + n0 + tx * 8;
        float4 v0, v1;
        v0.x = acc[i][0] + bsum[0];
        v0.y = acc[i][1] + bsum[1];
        v0.z = acc[i][2] + bsum[2];
        v0.w = acc[i][3] + bsum[3];
        v1.x = acc[i][4] + bsum[4];
        v1.y = acc[i][5] + bsum[5];
        v1.z = acc[i][6] + bsum[6];
        v1.w = acc[i][7] + bsum[7];
        *(float4*)(row)     = v0;
        *(float4*)(row + 4) = v1;
    }
}

// ---------------------------------------------------------------------------
// Sense-reversing grid barrier. All NBLK blocks are resident (grid <= SMs).
// ---------------------------------------------------------------------------
__device__ __forceinline__ void grid_barrier(int* lsense)
{
    __syncthreads();
    if (threadIdx.x == 0) {
        int ns = *lsense ^ 1;
        __threadfence();
        if (atomicAdd(&g_count, 1) == NBLK - 1) {
            g_count = 0;
            __threadfence();
            *(volatile int*)&g_sense = ns;
        } else {
            while (*(volatile int*)&g_sense != ns) { }
        }
        __threadfence();
        *lsense = ns;
    }
    __syncthreads();
}

// Named barrier for one 128-thread group (ids 1..4; id 0 is __syncthreads)
__device__ __forceinline__ void group_bar(int id)
{
    asm volatile("bar.sync %0, 128;" :: "r"(id) : "memory");
}

// sign-safe fast tanh via __expf (no overflow/NaN for any x)
__device__ __forceinline__ float fast_tanh(float x)
{
    float e = __expf(-2.f * fabsf(x));
    float t = __fdividef(1.f - e, 1.f + e);
    return copysignf(t, x);
}

// ---------------------------------------------------------------------------
// Kernel 2: persistent recurrence. 128 blocks x 512 threads, loops s=0..1023.
// Block owns 8 h-columns j0..j0+7 -> 32 gate columns:
//   gate col c (0..31) -> global gate index (c/8)*1024 + j0 + (c%8)
// 4-way split-K: group g = tid/128 accumulates K quarter [g*256, g*256+256),
// synced by its own named barrier so groups free-run independently.
// Within group: 64x32 tile, 128 threads, 4x4 micro (plain FFMA; the R5 FFMA2
// experiment was LDS-crossbar-bound and reverted).
// SMEM: per-group arena; Gs partials alias the group's Hs region (safe: Gs is
// written after the group's last Hs read, consumed before the grid barrier,
// and Hs is refilled only after it).
// c state lives in registers; Xg[t] prefetched at step start (hides DRAM);
// hprev streams via __ldcg so the Uw slice stays L1-resident.
// ---------------------------------------------------------------------------
#define NGRP 4
#define KC 32
#define NCHUNK 8    // 256 / KC per group
#define ARENA_F 3328  // floats per group: Hs 32*68=2176 + Us 32*36=1152

__shared__ __align__(16) float s_arena[NGRP][ARENA_F];
#define HS(g,k,i) s_arena[g][(k)*68 + (i)]
#define US(g,k,c) s_arena[g][2176 + (k)*36 + (c)]
#define GS(g,b,c) s_arena[g][(b)*33 + (c)]   // aliases HS region

__global__ __launch_bounds__(512) void lstm_persistent(
    const float* __restrict__ Uw,  // [4H, H]
    float* __restrict__ out)       // [2, NSTEP, B, H]
{
    const int tid = threadIdx.x;        // 512
    const int j0  = blockIdx.x * 8;     // 128 blocks
    const int g   = tid >> 7;           // K-quarter group 0..3
    const int gt  = tid & 127;
    const int tr  = gt & 15;            // rows 4*tr .. 4*tr+3
    const int tc  = gt >> 4;            // cols 4*tc .. 4*tc+3
    const int bar = g + 1;
    int lsense = 0;

    const size_t step_sz = (size_t)BB * HH;          // 65536
    const size_t c_base  = (size_t)NSTEP * step_sz;

    // Hs fill coordinates: 64 b x 32 k = 512 float4 per group, 4 per thread
    int hb[4], hk[4];
#pragma unroll
    for (int l = 0; l < 4; l++) {
        int fq = l * 128 + gt;          // 0..511
        hb[l] = fq >> 3;                // b 0..63
        hk[l] = (fq & 7) * 4;           // kq 0..28
    }
    // Us fill coordinates: 32 c x 32 k = 256 float4 per group, 2 per thread
    int uc[2], uk[2];
    size_t urow[2];
#pragma unroll
    for (int l = 0; l < 2; l++) {
        int fq = l * 128 + gt;          // 0..255
        uc[l] = fq >> 3;                // c 0..31
        uk[l] = (fq & 7) * 4;
        int gc = (uc[l] >> 3) * HH + j0 + (uc[l] & 7);
        urow[l] = (size_t)gc * HH;
    }
    const int kbase0 = g * 256;

    // Epilogue: 1 cell per thread, c register-resident
    const int eb = tid >> 3;            // b 0..63
    const int ej = tid & 7;             // jj 0..7
    float creg = 0.f;

    for (int s = 0; s < NSTEP; s++) {
        const int t = s >> 1;

        // Prefetch this step's Xg gate inputs (DRAM) — hides under the GEMM
        float xv0, xv1, xv2, xv3;
        {
            const float* xrow = g_xg + ((size_t)t * BB + eb) * G4 + j0 + ej;
            xv0 = __ldcg(xrow);
            xv1 = __ldcg(xrow + HH);
            xv2 = __ldcg(xrow + 2 * HH);
            xv3 = __ldcg(xrow + 3 * HH);
        }

        float acc[4][4];
#pragma unroll
        for (int i = 0; i < 4; i++)
#pragma unroll
            for (int j = 0; j < 4; j++) acc[i][j] = 0.f;

        if (s > 0) {
            const float* hprev = out + (size_t)(s - 1) * step_sz;

            // Prefetch chunk 0 into registers
            float4 hreg[4], ureg[2];
#pragma unroll
            for (int l = 0; l < 4; l++)
                hreg[l] = __ldcg((const float4*)(hprev + (size_t)hb[l] * HH + kbase0 + hk[l]));
#pragma unroll
            for (int l = 0; l < 2; l++)
                ureg[l] = *(const float4*)(Uw + urow[l] + kbase0 + uk[l]);

            for (int chunk = 0; chunk < NCHUNK; chunk++) {
                // Commit prefetched tile to this group's shared arena
#pragma unroll
                for (int l = 0; l < 4; l++) {
                    HS(g, hk[l] + 0, hb[l]) = hreg[l].x;
                    HS(g, hk[l] + 1, hb[l]) = hreg[l].y;
                    HS(g, hk[l] + 2, hb[l]) = hreg[l].z;
                    HS(g, hk[l] + 3, hb[l]) = hreg[l].w;
                }
#pragma unroll
                for (int l = 0; l < 2; l++) {
                    US(g, uk[l] + 0, uc[l]) = ureg[l].x;
                    US(g, uk[l] + 1, uc[l]) = ureg[l].y;
                    US(g, uk[l] + 2, uc[l]) = ureg[l].z;
                    US(g, uk[l] + 3, uc[l]) = ureg[l].w;
                }
                group_bar(bar);

                // Prefetch next chunk while computing this one
                if (chunk + 1 < NCHUNK) {
                    int kb = kbase0 + (chunk + 1) * KC;
#pragma unroll
                    for (int l = 0; l < 4; l++)
                        hreg[l] = __ldcg((const float4*)(hprev + (size_t)hb[l] * HH + kb + hk[l]));
#pragma unroll
                    for (int l = 0; l < 2; l++)
                        ureg[l] = *(const float4*)(Uw + urow[l] + kb + uk[l]);
                }

#pragma unroll
                for (int kk = 0; kk < KC; kk++) {
                    const float4 a  = *(const float4*)&HS(g, kk, 4 * tr);
                    const float4 bv = *(const float4*)&US(g, kk, 4 * tc);
                    acc[0][0] += a.x * bv.x; acc[0][1] += a.x * bv.y;
                    acc[0][2] += a.x * bv.z; acc[0][3] += a.x * bv.w;
                    acc[1][0] += a.y * bv.x; acc[1][1] += a.y * bv.y;
                    acc[1][2] += a.y * bv.z; acc[1][3] += a.y * bv.w;
                    acc[2][0] += a.z * bv.x; acc[2][1] += a.z * bv.y;
                    acc[2][2] += a.z * bv.z; acc[2][3] += a.z * bv.w;
                    acc[3][0] += a.w * bv.x; acc[3][1] += a.w * bv.y;
                    acc[3][2] += a.w * bv.z; acc[3][3] += a.w * bv.w;
                }
                group_bar(bar);   // all group warps done reading before refill
            }
        }

        // Stash group partials (GS aliases HS — group's GEMM is complete)
#pragma unroll
        for (int i = 0; i < 4; i++)
#pragma unroll
            for (int j = 0; j < 4; j++)
                GS(g, 4 * tr + i, 4 * tc + j) = acc[i][j];
        __syncthreads();

        // Fused LSTM cell epilogue: 512 cells, 1 per thread
        {
            const int b  = eb;
            const int jj = ej;
            const int j  = j0 + jj;

            float gi = GS(0, b, jj)      + GS(1, b, jj)      + GS(2, b, jj)      + GS(3, b, jj)      + xv0;
            float gf = GS(0, b, 8 + jj)  + GS(1, b, 8 + jj)  + GS(2, b, 8 + jj)  + GS(3, b, 8 + jj)  + xv1;
            float gg = GS(0, b, 16 + jj) + GS(1, b, 16 + jj) + GS(2, b, 16 + jj) + GS(3, b, 16 + jj) + xv2;
            float go = GS(0, b, 24 + jj) + GS(1, b, 24 + jj) + GS(2, b, 24 + jj) + GS(3, b, 24 + jj) + xv3;

            float si = __fdividef(1.f, 1.f + __expf(-gi));
            float sf = __fdividef(1.f, 1.f + __expf(-gf));
            float so = __fdividef(1.f, 1.f + __expf(-go));
            float tg = fast_tanh(gg);

            float cn = creg * sf + si * tg;
            float hn = so * fast_tanh(cn);
            creg = cn;

            out[(size_t)s * step_sz + (size_t)b * HH + j]          = hn;
            out[c_base + (size_t)s * step_sz + (size_t)b * HH + j] = cn;
        }

        // Publish h of step s to all blocks before step s+1 reads it.
        grid_barrier(&lsense);
    }
}

// ---------------------------------------------------------------------------
extern "C" void kernel_launch(void* const* d_in, const int* in_sizes, int n_in,
                              void* d_out, int out_size)
{
    const float* x  = (const float*)d_in[0];
    const float* Ww = (const float*)d_in[1];
    const float* bw = (const float*)d_in[2];
    const float* Uw = (const float*)d_in[3];
    const float* bu = (const float*)d_in[4];
    float* out = (float*)d_out;

    dim3 g1(G4 / XG_BN, (TT * BB) / XG_BM);  // (32, 256)
    xg_kernel<<<g1, 256>>>(x, Ww, bw, bu);

    lstm_persistent<<<NBLK, 512>>>(Uw, out);
}

// round 11
// speedup vs baseline: 3.4248x; 2.1549x over previous
#include <cuda_runtime.h>
#include <cuda_bf16.h>
#include <math.h>
#include <stdint.h>

// Problem constants
#define TT 512
#define BB 64
#define II 512
#define HH 1024
#define G4 4096
#define NSTEP 1024
#define NBLK 128     // persistent blocks, 1/SM, all co-resident

#define MT 32        // M rows per block (4 gates x 8 h-cols)
#define KCH 64       // K per chunk
#define NCH 16       // chunks per plane-K (1024/64)

// Scratch
__device__ float g_xg[(size_t)TT * BB * G4];                       // input projection
__device__ __align__(16) __nv_bfloat16 g_uws[2][NBLK][MT][HH];     // Uw split hi/lo per block
__device__ __align__(16) __nv_bfloat16 g_hs[2][2][BB][HH];         // h split [parity][plane][b][k]
__device__ int g_count;
__device__ int g_sense;

// ---------------------------------------------------------------------------
// SMEM layout (dynamic, 172544 B):
//   A planes (static per run): p*65536 + m*2048 + (u>>3)*128 + (((u&7)^(m&7))<<4)
//   B chunk buffers (x2):  131072 + buf*16384 + p*8192 + n*128 + (((u)^(n&7))<<4)
//   Gs gate stage: 163840 .. +32*68*4
// ---------------------------------------------------------------------------
#define SM_A(p, m, u)        ((p) * 65536 + (m) * 2048 + (((u) >> 3) << 7) + (((((u) & 7) ^ ((m) & 7))) << 4))
#define SM_B(buf, p, n, u)   (131072 + (buf) * 16384 + (p) * 8192 + (n) * 128 + ((((u) ^ ((n) & 7))) << 4))
#define SM_GS                163840
#define SMEM_BYTES           172544

// ---------------------------------------------------------------------------
// PTX helpers (all sm_80-class: compile for sm_103 target)
// ---------------------------------------------------------------------------
__device__ __forceinline__ uint32_t smem_u32(const void* p) {
    uint32_t a;
    asm("{ .reg .u64 t; cvta.to.shared.u64 t, %1; cvt.u32.u64 %0, t; }" : "=r"(a) : "l"(p));
    return a;
}
__device__ __forceinline__ void cpasync16(uint32_t dst, const void* src) {
    asm volatile("cp.async.cg.shared.global [%0], [%1], 16;" :: "r"(dst), "l"(src) : "memory");
}
#define CP_COMMIT()  asm volatile("cp.async.commit_group;" ::: "memory")
#define CP_WAIT(n)   asm volatile("cp.async.wait_group %0;" :: "n"(n) : "memory")

__device__ __forceinline__ void ldm_x4(uint32_t* r, uint32_t addr) {
    asm volatile("ldmatrix.sync.aligned.m8n8.x4.shared.b16 {%0,%1,%2,%3}, [%4];"
                 : "=r"(r[0]), "=r"(r[1]), "=r"(r[2]), "=r"(r[3]) : "r"(addr));
}
__device__ __forceinline__ void mma_bf16(float* d, const uint32_t* a, uint32_t b0, uint32_t b1) {
    asm volatile("mma.sync.aligned.m16n8k16.row.col.f32.bf16.bf16.f32 "
                 "{%0,%1,%2,%3}, {%4,%5,%6,%7}, {%8,%9}, {%0,%1,%2,%3};"
                 : "+f"(d[0]), "+f"(d[1]), "+f"(d[2]), "+f"(d[3])
                 : "r"(a[0]), "r"(a[1]), "r"(a[2]), "r"(a[3]), "r"(b0), "r"(b1));
}

// ---------------------------------------------------------------------------
// Kernel 1: Xg = x @ Ww.T + (bw + bu)   (proven FFMA version)
// ---------------------------------------------------------------------------
#define XG_BM 128
#define XG_BN 128
#define XG_BK 16

__global__ __launch_bounds__(256) void xg_kernel(
    const float* __restrict__ x, const float* __restrict__ Ww,
    const float* __restrict__ bw, const float* __restrict__ bu)
{
    __shared__ float As[XG_BK][XG_BM + 4];
    __shared__ float Bs[XG_BK][XG_BN + 4];

    const int tid = threadIdx.x;
    const int m0 = blockIdx.y * XG_BM;
    const int n0 = blockIdx.x * XG_BN;
    const int ty = tid >> 4, tx = tid & 15;

    float acc[8][8];
#pragma unroll
    for (int i = 0; i < 8; i++)
#pragma unroll
        for (int j = 0; j < 8; j++) acc[i][j] = 0.f;

    for (int k0 = 0; k0 < II; k0 += XG_BK) {
#pragma unroll
        for (int l = 0; l < 2; l++) {
            int fq = l * 256 + tid;
            int r = fq >> 2, kq = (fq & 3) * 4;
            int gr = m0 + r, b = gr & 63, t = gr >> 6;
            const float4 v = *(const float4*)(x + ((size_t)(b * TT + t)) * II + k0 + kq);
            As[kq + 0][r] = v.x; As[kq + 1][r] = v.y;
            As[kq + 2][r] = v.z; As[kq + 3][r] = v.w;
        }
#pragma unroll
        for (int l = 0; l < 2; l++) {
            int fq = l * 256 + tid;
            int n = fq >> 2, kq = (fq & 3) * 4;
            const float4 v = *(const float4*)(Ww + (size_t)(n0 + n) * II + k0 + kq);
            Bs[kq + 0][n] = v.x; Bs[kq + 1][n] = v.y;
            Bs[kq + 2][n] = v.z; Bs[kq + 3][n] = v.w;
        }
        __syncthreads();
#pragma unroll
        for (int kk = 0; kk < XG_BK; kk++) {
            float a[8], bb[8];
#pragma unroll
            for (int i = 0; i < 8; i++) a[i] = As[kk][ty * 8 + i];
#pragma unroll
            for (int j = 0; j < 8; j++) bb[j] = Bs[kk][tx * 8 + j];
#pragma unroll
            for (int i = 0; i < 8; i++)
#pragma unroll
                for (int j = 0; j < 8; j++) acc[i][j] += a[i] * bb[j];
        }
        __syncthreads();
    }

    float bsum[8];
#pragma unroll
    for (int j = 0; j < 8; j++) {
        int gn = n0 + tx * 8 + j;
        bsum[j] = bw[gn] + bu[gn];
    }
#pragma unroll
    for (int i = 0; i < 8; i++) {
        int gm = m0 + ty * 8 + i;
        float* row = g_xg + (size_t)gm * G4 + n0 + tx * 8;
        float4 v0, v1;
        v0.x = acc[i][0] + bsum[0]; v0.y = acc[i][1] + bsum[1];
        v0.z = acc[i][2] + bsum[2]; v0.w = acc[i][3] + bsum[3];
        v1.x = acc[i][4] + bsum[4]; v1.y = acc[i][5] + bsum[5];
        v1.z = acc[i][6] + bsum[6]; v1.w = acc[i][7] + bsum[7];
        *(float4*)(row) = v0; *(float4*)(row + 4) = v1;
    }
}

// ---------------------------------------------------------------------------
// Kernel 1b: split permuted Uw into bf16 hi/lo planes.
// Block blk, row m (= g*8 + jj) -> Uw row g*1024 + blk*8 + jj.
// ---------------------------------------------------------------------------
__global__ __launch_bounds__(256) void prep_uw(const float* __restrict__ Uw)
{
    size_t idx = (size_t)blockIdx.x * 256 + threadIdx.x;  // over 128*32*1024
    int k   = (int)(idx & 1023);
    int m   = (int)((idx >> 10) & 31);
    int blk = (int)(idx >> 15);
    int r = (m >> 3) * HH + blk * 8 + (m & 7);
    float v = Uw[(size_t)r * HH + k];
    __nv_bfloat16 hi = __float2bfloat16(v);
    float lo = v - __bfloat162float(hi);
    g_uws[0][blk][m][k] = hi;
    g_uws[1][blk][m][k] = __float2bfloat16(lo);
}

// ---------------------------------------------------------------------------
// Grid barrier (128 co-resident blocks), sense-reversing
// ---------------------------------------------------------------------------
__device__ __forceinline__ void grid_barrier(int* lsense)
{
    __syncthreads();
    if (threadIdx.x == 0) {
        int ns = *lsense ^ 1;
        __threadfence();
        if (atomicAdd(&g_count, 1) == NBLK - 1) {
            g_count = 0;
            __threadfence();
            *(volatile int*)&g_sense = ns;
        } else {
            while (*(volatile int*)&g_sense != ns) { }
        }
        __threadfence();
        *lsense = ns;
    }
    __syncthreads();
}

__device__ __forceinline__ float fast_tanh(float x)
{
    float e = __expf(-2.f * fabsf(x));
    float t = __fdividef(1.f - e, 1.f + e);
    return copysignf(t, x);
}

// ---------------------------------------------------------------------------
// Kernel 2: persistent mma.sync recurrence. 128 blocks x 256 threads.
// D[32,64] = 3-term bf16-split over K=1024: Ahi*Bhi + Ahi*Blo + Alo*Bhi.
// A (Uw planes) resident in SMEM all run; B (h planes) streamed per 64-chunk
// via cp.async double buffer.
// FIX (R10): B is stored [n=b][k] row-major; the mma.row.col B fragment needs
// k-consecutive pairs at fixed n, which NON-trans ldmatrix delivers (threads
// point at n-rows). The previous .trans load scrambled (k,n) -> rel_err 0.257.
// ---------------------------------------------------------------------------
extern __shared__ __align__(128) unsigned char smraw[];

__global__ void __launch_bounds__(256, 1) lstm_persistent(float* __restrict__ out)
{
    const int tid  = threadIdx.x;
    const int wid  = tid >> 5;
    const int lane = tid & 31;
    const int blk  = blockIdx.x;
    const int mw   = wid & 1;          // m16 tile
    const int nw   = wid >> 1;         // n16 tile (two n8 subtiles)
    const uint32_t smb = smem_u32(smraw);
    int lsense = 0;

    const size_t step_sz = (size_t)BB * HH;
    const size_t c_base  = (size_t)NSTEP * step_sz;

    // ---- one-time A fill: 2 planes x 32 rows x 128 units ----
    for (int l = 0; l < 32; l++) {
        int i = l * 256 + tid;          // 0..8191
        int u = i & 127, m = (i >> 7) & 31, p = i >> 12;
        const float4 v = *(const float4*)&g_uws[p][blk][m][u * 8];
        *(float4*)(smraw + SM_A(p, m, u)) = v;
    }
    __syncthreads();

    // ---- ldmatrix thread-role constants ----
    const int q  = lane >> 3;           // matrix index 0..3
    const int rr = lane & 7;
    // A: m0: q0 rows0-7/k0, q1 rows8-15/k0, q2 rows0-7/k+8, q3 rows8-15/k+8
    const int arow = 16 * mw + rr + 8 * (q & 1);
    const int adu  = (q >> 1);
    // B (non-trans from [n][k]): q0 n0-7/k0 (b0), q1 n0-7/k+8 (b1),
    //                            q2 n8-15/k0,     q3 n8-15/k+8
    const int brow = 16 * nw + rr + 8 * (q >> 1);
    const int bdu  = (q & 1);

    // ---- B-chunk fill coords: 4 cp.async(16B) per thread ----
    int fp[4], fn[4], fu[4];
    uint32_t fdst[4];
#pragma unroll
    for (int l = 0; l < 4; l++) {
        int i = l * 256 + tid;          // 0..1023
        fu[l] = i & 7;
        fn[l] = (i >> 3) & 63;
        fp[l] = i >> 9;
        fdst[l] = smb + SM_B(0, fp[l], fn[l], fu[l]);   // buf0; buf1 = +16384
    }

    // ---- epilogue cell coords: 2 cells/thread, c in registers ----
    int eb[2], ej[2];
    float creg[2] = {0.f, 0.f};
#pragma unroll
    for (int l = 0; l < 2; l++) {
        int idx = l * 256 + tid;        // 0..511
        eb[l] = idx >> 3;               // batch
        ej[l] = idx & 7;                // jj
    }

    float* gst = (float*)(smraw + SM_GS);   // Gs[m][b], stride 68

    for (int s = 0; s < NSTEP; s++) {
        const int t = s >> 1;

        // Prefetch Xg (8 values) — hidden under the GEMM
        float xv[2][4];
#pragma unroll
        for (int l = 0; l < 2; l++) {
            const float* xb = g_xg + ((size_t)t * BB + eb[l]) * G4 + blk * 8 + ej[l];
#pragma unroll
            for (int gg = 0; gg < 4; gg++)
                xv[l][gg] = __ldcg(xb + gg * HH);
        }

        float d[2][4];                   // [n8 subtile][frag reg]
#pragma unroll
        for (int i = 0; i < 2; i++)
#pragma unroll
            for (int j = 0; j < 4; j++) d[i][j] = 0.f;

        if (s > 0) {
            const int par = (s - 1) & 1;

            // prologue: fill chunk 0 into buf 0
#pragma unroll
            for (int l = 0; l < 4; l++)
                cpasync16(fdst[l], &g_hs[par][fp[l]][fn[l]][fu[l] * 8]);
            CP_COMMIT();

            for (int c = 0; c < NCH; c++) {
                const int buf = c & 1;
                if (c + 1 < NCH) {
                    const int nb = (c + 1) & 1;
#pragma unroll
                    for (int l = 0; l < 4; l++)
                        cpasync16(fdst[l] + nb * 16384,
                                  &g_hs[par][fp[l]][fn[l]][(c + 1) * KCH + fu[l] * 8]);
                    CP_COMMIT();
                    CP_WAIT(1);
                } else {
                    CP_WAIT(0);
                }
                __syncthreads();

#pragma unroll
                for (int kk = 0; kk < 4; kk++) {
                    const int ua = c * 8 + kk * 2 + adu;    // A unit (global k)
                    const int ub = kk * 2 + bdu;            // B unit (chunk-local)
                    uint32_t ah[4], al[4], bh[4], bl[4];
                    ldm_x4(ah, smb + SM_A(0, arow, ua));
                    ldm_x4(al, smb + SM_A(1, arow, ua));
                    ldm_x4(bh, smb + SM_B(buf, 0, brow, ub));   // non-trans (FIX)
                    ldm_x4(bl, smb + SM_B(buf, 1, brow, ub));   // non-trans (FIX)
                    // hi*hi
                    mma_bf16(d[0], ah, bh[0], bh[1]);
                    mma_bf16(d[1], ah, bh[2], bh[3]);
                    // hi*lo
                    mma_bf16(d[0], ah, bl[0], bl[1]);
                    mma_bf16(d[1], ah, bl[2], bl[3]);
                    // lo*hi
                    mma_bf16(d[0], al, bh[0], bh[1]);
                    mma_bf16(d[1], al, bh[2], bh[3]);
                }
                __syncthreads();
            }

            // D fragments -> Gs[m][b]
            {
                const int r  = 16 * mw + (lane >> 2);
                const int cb = 2 * (lane & 3);
#pragma unroll
                for (int tt2 = 0; tt2 < 2; tt2++) {
                    const int n0t = 16 * nw + 8 * tt2;
                    gst[(r)     * 68 + n0t + cb]     = d[tt2][0];
                    gst[(r)     * 68 + n0t + cb + 1] = d[tt2][1];
                    gst[(r + 8) * 68 + n0t + cb]     = d[tt2][2];
                    gst[(r + 8) * 68 + n0t + cb + 1] = d[tt2][3];
                }
            }
        }
        __syncthreads();

        // Fused LSTM cell epilogue: 2 cells per thread
#pragma unroll
        for (int l = 0; l < 2; l++) {
            const int b  = eb[l];
            const int jj = ej[l];
            const int j  = blk * 8 + jj;

            float gi, gf, gg_, go;
            if (s > 0) {
                gi  = gst[(0 * 8 + jj) * 68 + b] + xv[l][0];
                gf  = gst[(1 * 8 + jj) * 68 + b] + xv[l][1];
                gg_ = gst[(2 * 8 + jj) * 68 + b] + xv[l][2];
                go  = gst[(3 * 8 + jj) * 68 + b] + xv[l][3];
            } else {
                gi = xv[l][0]; gf = xv[l][1]; gg_ = xv[l][2]; go = xv[l][3];
            }

            float si = __fdividef(1.f, 1.f + __expf(-gi));
            float sf = __fdividef(1.f, 1.f + __expf(-gf));
            float so = __fdividef(1.f, 1.f + __expf(-go));
            float tg = fast_tanh(gg_);

            float cn = creg[l] * sf + si * tg;
            float hn = so * fast_tanh(cn);
            creg[l] = cn;

            out[(size_t)s * step_sz + (size_t)b * HH + j]          = hn;
            out[c_base + (size_t)s * step_sz + (size_t)b * HH + j] = cn;

            __nv_bfloat16 hi = __float2bfloat16(hn);
            float lo = hn - __bfloat162float(hi);
            g_hs[s & 1][0][b][j] = hi;
            g_hs[s & 1][1][b][j] = __float2bfloat16(lo);
        }

        // Publish h of step s before step s+1 reads it.
        grid_barrier(&lsense);
    }
}

// ---------------------------------------------------------------------------
extern "C" void kernel_launch(void* const* d_in, const int* in_sizes, int n_in,
                              void* d_out, int out_size)
{
    const float* x  = (const float*)d_in[0];
    const float* Ww = (const float*)d_in[1];
    const float* bw = (const float*)d_in[2];
    const float* Uw = (const float*)d_in[3];
    const float* bu = (const float*)d_in[4];
    float* out = (float*)d_out;

    dim3 g1(G4 / XG_BN, (TT * BB) / XG_BM);
    xg_kernel<<<g1, 256>>>(x, Ww, bw, bu);

    prep_uw<<<(NBLK * MT * HH) / 256, 256>>>(Uw);

    cudaFuncSetAttribute(lstm_persistent,
                         cudaFuncAttributeMaxDynamicSharedMemorySize, SMEM_BYTES);
    lstm_persistent<<<NBLK, 256, SMEM_BYTES>>>(out);
}

// round 13
// speedup vs baseline: 4.0278x; 1.1761x over previous
#include <cuda_runtime.h>
#include <cuda_bf16.h>
#include <math.h>
#include <stdint.h>

// Problem constants
#define TT 512
#define BB 64
#define II 512
#define HH 1024
#define G4 4096
#define NSTEP 1024
#define NBLK 128     // persistent blocks, 1/SM, all co-resident

#define MT 32        // M rows per recurrence block (4 gates x 8 h-cols)
#define KCH 64       // K per chunk
#define NCH 16       // chunks (1024/64)

// Scratch
__device__ float g_xg[(size_t)TT * BB * G4];                       // input projection (fp32)
__device__ __align__(16) __nv_bfloat16 g_uws[2][NBLK][MT][HH];     // Uw split hi/lo per block
__device__ __align__(16) __nv_bfloat16 g_hs[2][2][BB][HH];         // h split [parity][plane][b][k]
__device__ __align__(16) __nv_bfloat16 g_xs[2][(size_t)TT * BB][II]; // x split, rows = t*64+b
__device__ __align__(16) __nv_bfloat16 g_ws[2][G4][II];            // Ww split hi/lo
__device__ float g_bsum[G4];                                       // bw + bu
__device__ int g_count;
__device__ int g_sense;

// ---------------------------------------------------------------------------
// Recurrence SMEM layout (dynamic, 188928 B):
//   A planes (static per run): p*65536 + m*2048 + (u>>3)*128 + swz   -> 131072
//   B chunk ring (x3, 16KB):   131072 + buf*16384 + p*8192 + n*128 + swz
//   Gs gate stage:             180224 .. +32*68*4
// ---------------------------------------------------------------------------
#define SM_A(p, m, u)        ((p) * 65536 + (m) * 2048 + (((u) >> 3) << 7) + (((((u) & 7) ^ ((m) & 7))) << 4))
#define SM_B(buf, p, n, u)   (131072 + (buf) * 16384 + (p) * 8192 + (n) * 128 + ((((u) ^ ((n) & 7))) << 4))
#define SM_GS                180224
#define SMEM_BYTES           188928

// xg_mma SMEM layout (dynamic, 131072 B): 2 bufs x (A 32KB + B 32KB)
#define XSA(buf, p, r, u)    ((buf) * 32768 + (p) * 16384 + (r) * 128 + ((((u) ^ ((r) & 7))) << 4))
#define XSB(buf, p, n, u)    (65536 + (buf) * 32768 + (p) * 16384 + (n) * 128 + ((((u) ^ ((n) & 7))) << 4))
#define XSMEM_BYTES          131072

// ---------------------------------------------------------------------------
// PTX helpers (sm_80-class)
// ---------------------------------------------------------------------------
__device__ __forceinline__ uint32_t smem_u32(const void* p) {
    uint32_t a;
    asm("{ .reg .u64 t; cvta.to.shared.u64 t, %1; cvt.u32.u64 %0, t; }" : "=r"(a) : "l"(p));
    return a;
}
__device__ __forceinline__ void cpasync16(uint32_t dst, const void* src) {
    asm volatile("cp.async.cg.shared.global [%0], [%1], 16;" :: "r"(dst), "l"(src) : "memory");
}
#define CP_COMMIT()  asm volatile("cp.async.commit_group;" ::: "memory")
#define CP_WAIT(n)   asm volatile("cp.async.wait_group %0;" :: "n"(n) : "memory")

__device__ __forceinline__ void ldm_x4(uint32_t* r, uint32_t addr) {
    asm volatile("ldmatrix.sync.aligned.m8n8.x4.shared.b16 {%0,%1,%2,%3}, [%4];"
                 : "=r"(r[0]), "=r"(r[1]), "=r"(r[2]), "=r"(r[3]) : "r"(addr));
}
__device__ __forceinline__ void mma_bf16(float* d, const uint32_t* a, uint32_t b0, uint32_t b1) {
    asm volatile("mma.sync.aligned.m16n8k16.row.col.f32.bf16.bf16.f32 "
                 "{%0,%1,%2,%3}, {%4,%5,%6,%7}, {%8,%9}, {%0,%1,%2,%3};"
                 : "+f"(d[0]), "+f"(d[1]), "+f"(d[2]), "+f"(d[3])
                 : "r"(a[0]), "r"(a[1]), "r"(a[2]), "r"(a[3]), "r"(b0), "r"(b1));
}

// ---------------------------------------------------------------------------
// Prep: split x (permuted rows gm = t*64+b) and Ww into bf16 hi/lo planes
// ---------------------------------------------------------------------------
__global__ __launch_bounds__(256) void split_x(const float* __restrict__ x)
{
    size_t idx = (size_t)blockIdx.x * 256 + threadIdx.x;   // over 32768*512
    int k  = (int)(idx & 511);
    int gm = (int)(idx >> 9);
    int t = gm >> 6, b = gm & 63;
    float v = x[((size_t)(b * TT + t)) * II + k];
    __nv_bfloat16 hi = __float2bfloat16(v);
    float lo = v - __bfloat162float(hi);
    g_xs[0][gm][k] = hi;
    g_xs[1][gm][k] = __float2bfloat16(lo);
}

__global__ __launch_bounds__(256) void split_w(const float* __restrict__ Ww,
                                               const float* __restrict__ bw,
                                               const float* __restrict__ bu)
{
    size_t idx = (size_t)blockIdx.x * 256 + threadIdx.x;   // over 4096*512
    int k = (int)(idx & 511);
    int n = (int)(idx >> 9);
    float v = Ww[(size_t)n * II + k];
    __nv_bfloat16 hi = __float2bfloat16(v);
    float lo = v - __bfloat162float(hi);
    g_ws[0][n][k] = hi;
    g_ws[1][n][k] = __float2bfloat16(lo);
    if (k == 0) g_bsum[n] = bw[n] + bu[n];
}

// ---------------------------------------------------------------------------
// Kernel 1b: split permuted Uw into bf16 hi/lo planes (unchanged, proven)
// ---------------------------------------------------------------------------
__global__ __launch_bounds__(256) void prep_uw(const float* __restrict__ Uw)
{
    size_t idx = (size_t)blockIdx.x * 256 + threadIdx.x;  // over 128*32*1024
    int k   = (int)(idx & 1023);
    int m   = (int)((idx >> 10) & 31);
    int blk = (int)(idx >> 15);
    int r = (m >> 3) * HH + blk * 8 + (m & 7);
    float v = Uw[(size_t)r * HH + k];
    __nv_bfloat16 hi = __float2bfloat16(v);
    float lo = v - __bfloat162float(hi);
    g_uws[0][blk][m][k] = hi;
    g_uws[1][blk][m][k] = __float2bfloat16(lo);
}

extern __shared__ __align__(128) unsigned char smraw[];

// ---------------------------------------------------------------------------
// Kernel 1: Xg via tensor cores. Grid (32, 256), 256 thr.
// Block: M=128 rows (gm0..), N=128 gates (n0..), K=512 in 8 chunks of 64.
// Same validated fragment mapping as the recurrence; 2-buffer cp.async,
// 2 syncs per chunk (proven-safe pattern). D += bias -> g_xg fp32.
// Warp w: wr=w&3 -> rows 32wr..+31 (2 m16), wc=w>>2 -> cols 64wc..+63 (4 n16).
// ---------------------------------------------------------------------------
__global__ void __launch_bounds__(256, 1) xg_mma()
{
    const int tid  = threadIdx.x;
    const int wid  = tid >> 5;
    const int lane = tid & 31;
    const int wr = wid & 3, wc = wid >> 2;
    const int gm0 = blockIdx.y * 128;
    const int n0  = blockIdx.x * 128;
    const uint32_t smb = smem_u32(smraw);

    const int q  = lane >> 3;
    const int rr = lane & 7;
    const int arow = 32 * wr + rr + 8 * (q & 1);   // + 16*mt
    const int adu  = q >> 1;
    const int brow = 64 * wc + rr + 8 * (q >> 1);  // + 16*nt
    const int bdu  = q & 1;

    // fill coords: 8 A units + 8 B units per thread per chunk
    int ap_[8], ar_[8], au_[8];
    uint32_t adst_[8], bdst_[8];
#pragma unroll
    for (int l = 0; l < 8; l++) {
        int i = l * 256 + tid;           // 0..2047
        au_[l] = i & 7;
        ar_[l] = (i >> 3) & 127;
        ap_[l] = i >> 10;
        adst_[l] = smb + XSA(0, ap_[l], ar_[l], au_[l]);
        bdst_[l] = smb + XSB(0, ap_[l], ar_[l], au_[l]);
    }

    float d[2][8][4];
#pragma unroll
    for (int mt = 0; mt < 2; mt++)
#pragma unroll
        for (int f = 0; f < 8; f++)
#pragma unroll
            for (int j = 0; j < 4; j++) d[mt][f][j] = 0.f;

    // prologue: chunk 0 -> buf 0
#pragma unroll
    for (int l = 0; l < 8; l++) {
        cpasync16(adst_[l], &g_xs[ap_[l]][gm0 + ar_[l]][au_[l] * 8]);
        cpasync16(bdst_[l], &g_ws[ap_[l]][n0 + ar_[l]][au_[l] * 8]);
    }
    CP_COMMIT();

    for (int c = 0; c < 8; c++) {
        const int bufo = (c & 1) * 32768;
        if (c + 1 < 8) {
            const int nbo = ((c + 1) & 1) * 32768;
            const int k0 = (c + 1) * 64;
#pragma unroll
            for (int l = 0; l < 8; l++) {
                cpasync16(adst_[l] + nbo, &g_xs[ap_[l]][gm0 + ar_[l]][k0 + au_[l] * 8]);
                cpasync16(bdst_[l] + nbo, &g_ws[ap_[l]][n0 + ar_[l]][k0 + au_[l] * 8]);
            }
            CP_COMMIT();
            CP_WAIT(1);
        } else {
            CP_WAIT(0);
        }
        __syncthreads();

#pragma unroll
        for (int kk = 0; kk < 4; kk++) {
            const int ua = kk * 2 + adu;
            const int ub = kk * 2 + bdu;
            uint32_t ah[2][4], al[2][4], bh[4][4], bl[4][4];
#pragma unroll
            for (int mt = 0; mt < 2; mt++) {
                const int rA = arow + 16 * mt;
                ldm_x4(ah[mt], smb + bufo + XSA(0, 0, rA, ua));
                ldm_x4(al[mt], smb + bufo + XSA(0, 1, rA, ua));
            }
#pragma unroll
            for (int nt = 0; nt < 4; nt++) {
                const int rB = brow + 16 * nt;
                ldm_x4(bh[nt], smb + bufo + XSB(0, 0, rB, ub));
                ldm_x4(bl[nt], smb + bufo + XSB(0, 1, rB, ub));
            }
#pragma unroll
            for (int mt = 0; mt < 2; mt++)
#pragma unroll
                for (int nt = 0; nt < 4; nt++) {
                    mma_bf16(d[mt][nt * 2 + 0], ah[mt], bh[nt][0], bh[nt][1]);
                    mma_bf16(d[mt][nt * 2 + 1], ah[mt], bh[nt][2], bh[nt][3]);
                    mma_bf16(d[mt][nt * 2 + 0], ah[mt], bl[nt][0], bl[nt][1]);
                    mma_bf16(d[mt][nt * 2 + 1], ah[mt], bl[nt][2], bl[nt][3]);
                    mma_bf16(d[mt][nt * 2 + 0], al[mt], bh[nt][0], bh[nt][1]);
                    mma_bf16(d[mt][nt * 2 + 1], al[mt], bh[nt][2], bh[nt][3]);
                }
        }
        __syncthreads();
    }

    // epilogue: bias + store fp32
    const int r0 = 32 * wr + (lane >> 2);
    const int cb = 2 * (lane & 3);
#pragma unroll
    for (int mt = 0; mt < 2; mt++)
#pragma unroll
        for (int nt = 0; nt < 4; nt++)
#pragma unroll
            for (int sub = 0; sub < 2; sub++) {
                const int n  = 64 * wc + 16 * nt + 8 * sub + cb;
                const int gn = n0 + n;
                const float b0 = g_bsum[gn], b1 = g_bsum[gn + 1];
                const int r = r0 + 16 * mt;
                const float* fr = d[mt][nt * 2 + sub];
                float2 v0 = make_float2(fr[0] + b0, fr[1] + b1);
                float2 v1 = make_float2(fr[2] + b0, fr[3] + b1);
                *(float2*)(g_xg + (size_t)(gm0 + r) * G4 + gn)     = v0;
                *(float2*)(g_xg + (size_t)(gm0 + r + 8) * G4 + gn) = v1;
            }
}

// ---------------------------------------------------------------------------
// Grid barrier (128 co-resident blocks) — UNCHANGED (proven)
// ---------------------------------------------------------------------------
__device__ __forceinline__ void grid_barrier(int* lsense)
{
    __syncthreads();
    if (threadIdx.x == 0) {
        int ns = *lsense ^ 1;
        __threadfence();
        if (atomicAdd(&g_count, 1) == NBLK - 1) {
            g_count = 0;
            __threadfence();
            *(volatile int*)&g_sense = ns;
        } else {
            while (*(volatile int*)&g_sense != ns) { }
        }
        __threadfence();
        *lsense = ns;
    }
    __syncthreads();
}

__device__ __forceinline__ float fast_tanh(float x)
{
    float e = __expf(-2.f * fabsf(x));
    float t = __fdividef(1.f - e, 1.f + e);
    return copysignf(t, x);
}

// ---------------------------------------------------------------------------
// Kernel 2: persistent mma.sync recurrence (R10-proven), with a 3-buffer
// cp.async ring and ONE __syncthreads per chunk:
//   fill(c+1)->buf (c+1)%3 can never collide with a straggler computing c-1
//   (buffers differ mod 3); the leading sync publishes chunk c cross-thread.
// ---------------------------------------------------------------------------
__global__ void __launch_bounds__(256, 1) lstm_persistent(float* __restrict__ out)
{
    const int tid  = threadIdx.x;
    const int wid  = tid >> 5;
    const int lane = tid & 31;
    const int blk  = blockIdx.x;
    const int mw   = wid & 1;
    const int nw   = wid >> 1;
    const uint32_t smb = smem_u32(smraw);
    int lsense = 0;

    const size_t step_sz = (size_t)BB * HH;
    const size_t c_base  = (size_t)NSTEP * step_sz;

    // one-time A fill
    for (int l = 0; l < 32; l++) {
        int i = l * 256 + tid;
        int u = i & 127, m = (i >> 7) & 31, p = i >> 12;
        const float4 v = *(const float4*)&g_uws[p][blk][m][u * 8];
        *(float4*)(smraw + SM_A(p, m, u)) = v;
    }
    __syncthreads();

    const int q  = lane >> 3;
    const int rr = lane & 7;
    const int arow = 16 * mw + rr + 8 * (q & 1);
    const int adu  = (q >> 1);
    const int brow = 16 * nw + rr + 8 * (q >> 1);
    const int bdu  = (q & 1);

    int fp[4], fn[4], fu[4];
    uint32_t fdst[4];
#pragma unroll
    for (int l = 0; l < 4; l++) {
        int i = l * 256 + tid;
        fu[l] = i & 7;
        fn[l] = (i >> 3) & 63;
        fp[l] = i >> 9;
        fdst[l] = smb + SM_B(0, fp[l], fn[l], fu[l]);   // +16384 per buf
    }

    int eb[2], ej[2];
    float creg[2] = {0.f, 0.f};
#pragma unroll
    for (int l = 0; l < 2; l++) {
        int idx = l * 256 + tid;
        eb[l] = idx >> 3;
        ej[l] = idx & 7;
    }

    float* gst = (float*)(smraw + SM_GS);

    for (int s = 0; s < NSTEP; s++) {
        const int t = s >> 1;

        float xv[2][4];
#pragma unroll
        for (int l = 0; l < 2; l++) {
            const float* xb = g_xg + ((size_t)t * BB + eb[l]) * G4 + blk * 8 + ej[l];
#pragma unroll
            for (int gg = 0; gg < 4; gg++)
                xv[l][gg] = __ldcg(xb + gg * HH);
        }

        float d[2][4];
#pragma unroll
        for (int i = 0; i < 2; i++)
#pragma unroll
            for (int j = 0; j < 4; j++) d[i][j] = 0.f;

        if (s > 0) {
            const int par = (s - 1) & 1;

            // prologue: chunk 0 -> buf 0
#pragma unroll
            for (int l = 0; l < 4; l++)
                cpasync16(fdst[l], &g_hs[par][fp[l]][fn[l]][fu[l] * 8]);
            CP_COMMIT();

            for (int c = 0; c < NCH; c++) {
                if (c + 1 < NCH) {
                    const int nb = (c + 1) % 3;
#pragma unroll
                    for (int l = 0; l < 4; l++)
                        cpasync16(fdst[l] + nb * 16384,
                                  &g_hs[par][fp[l]][fn[l]][(c + 1) * KCH + fu[l] * 8]);
                    CP_COMMIT();
                    CP_WAIT(1);
                } else {
                    CP_WAIT(0);
                }
                __syncthreads();   // chunk c visible to all; compute c-1 done

                const int bufo = (c % 3) * 16384;
#pragma unroll
                for (int kk = 0; kk < 4; kk++) {
                    const int ua = c * 8 + kk * 2 + adu;
                    const int ub = kk * 2 + bdu;
                    uint32_t ah[4], al[4], bh[4], bl[4];
                    ldm_x4(ah, smb + SM_A(0, arow, ua));
                    ldm_x4(al, smb + SM_A(1, arow, ua));
                    ldm_x4(bh, smb + bufo + SM_B(0, 0, brow, ub));
                    ldm_x4(bl, smb + bufo + SM_B(0, 1, brow, ub));
                    mma_bf16(d[0], ah, bh[0], bh[1]);
                    mma_bf16(d[1], ah, bh[2], bh[3]);
                    mma_bf16(d[0], ah, bl[0], bl[1]);
                    mma_bf16(d[1], ah, bl[2], bl[3]);
                    mma_bf16(d[0], al, bh[0], bh[1]);
                    mma_bf16(d[1], al, bh[2], bh[3]);
                }
            }

            // D fragments -> Gs[m][b]
            {
                const int r  = 16 * mw + (lane >> 2);
                const int cb = 2 * (lane & 3);
#pragma unroll
                for (int tt2 = 0; tt2 < 2; tt2++) {
                    const int n0t = 16 * nw + 8 * tt2;
                    gst[(r)     * 68 + n0t + cb]     = d[tt2][0];
                    gst[(r)     * 68 + n0t + cb + 1] = d[tt2][1];
                    gst[(r + 8) * 68 + n0t + cb]     = d[tt2][2];
                    gst[(r + 8) * 68 + n0t + cb + 1] = d[tt2][3];
                }
            }
        }
        __syncthreads();

        // Fused LSTM cell epilogue
#pragma unroll
        for (int l = 0; l < 2; l++) {
            const int b  = eb[l];
            const int jj = ej[l];
            const int j  = blk * 8 + jj;

            float gi, gf, gg_, go;
            if (s > 0) {
                gi  = gst[(0 * 8 + jj) * 68 + b] + xv[l][0];
                gf  = gst[(1 * 8 + jj) * 68 + b] + xv[l][1];
                gg_ = gst[(2 * 8 + jj) * 68 + b] + xv[l][2];
                go  = gst[(3 * 8 + jj) * 68 + b] + xv[l][3];
            } else {
                gi = xv[l][0]; gf = xv[l][1]; gg_ = xv[l][2]; go = xv[l][3];
            }

            float si = __fdividef(1.f, 1.f + __expf(-gi));
            float sf = __fdividef(1.f, 1.f + __expf(-gf));
            float so = __fdividef(1.f, 1.f + __expf(-go));
            float tg = fast_tanh(gg_);

            float cn = creg[l] * sf + si * tg;
            float hn = so * fast_tanh(cn);
            creg[l] = cn;

            out[(size_t)s * step_sz + (size_t)b * HH + j]          = hn;
            out[c_base + (size_t)s * step_sz + (size_t)b * HH + j] = cn;

            __nv_bfloat16 hi = __float2bfloat16(hn);
            float lo = hn - __bfloat162float(hi);
            g_hs[s & 1][0][b][j] = hi;
            g_hs[s & 1][1][b][j] = __float2bfloat16(lo);
        }

        grid_barrier(&lsense);
    }
}

// ---------------------------------------------------------------------------
extern "C" void kernel_launch(void* const* d_in, const int* in_sizes, int n_in,
                              void* d_out, int out_size)
{
    const float* x  = (const float*)d_in[0];
    const float* Ww = (const float*)d_in[1];
    const float* bw = (const float*)d_in[2];
    const float* Uw = (const float*)d_in[3];
    const float* bu = (const float*)d_in[4];
    float* out = (float*)d_out;

    split_x<<<(TT * BB * II) / 256, 256>>>(x);
    split_w<<<(G4 * II) / 256, 256>>>(Ww, bw, bu);

    cudaFuncSetAttribute(xg_mma,
                         cudaFuncAttributeMaxDynamicSharedMemorySize, XSMEM_BYTES);
    xg_mma<<<dim3(G4 / 128, (TT * BB) / 128), 256, XSMEM_BYTES>>>();

    prep_uw<<<(NBLK * MT * HH) / 256, 256>>>(Uw);

    cudaFuncSetAttribute(lstm_persistent,
                         cudaFuncAttributeMaxDynamicSharedMemorySize, SMEM_BYTES);
    lstm_persistent<<<NBLK, 256, SMEM_BYTES>>>(out);
}